// round 1
// baseline (speedup 1.0000x reference)
#include <cuda_runtime.h>
#include <cuda_bf16.h>
#include <math.h>

// Problem constants
#define BSn   2
#define Cn    256
#define Hn    200
#define Wn    200
#define HWn   (Hn * Wn)          // 40000
#define Mn    (BSn * HWn)        // 80000
#define NLAYERS 3
#define HEADSn 8
#define POINTSn 4
#define HDn   32                 // Cn / HEADSn

// -------- scratch (static device arrays; no allocation allowed) ----------
__device__ float g_out [ (size_t)Mn * Cn ];   // running activations [b,hw,c]
__device__ float g_pos [ (size_t)HWn * Cn ];  // sine positional encoding
__device__ float g_val [ (size_t)Mn * Cn ];   // value / attn2 / ffn2 scratch
__device__ float g_attn[ (size_t)Mn * Cn ];   // xbuf / attn / ffn1 scratch
__device__ float g_off [ (size_t)Mn * 64 ];
__device__ float g_aw  [ (size_t)Mn * 32 ];

// ======================= generic 32x32 tiled transpose ====================
// src: [z][P][Q] -> dst: [z][Q][P]
__global__ void transpose_kernel(const float* __restrict__ src,
                                 float* __restrict__ dst, int P, int Q)
{
    __shared__ float tile[32][33];
    size_t zoff = (size_t)blockIdx.z * (size_t)P * (size_t)Q;
    src += zoff; dst += zoff;
    int q0 = blockIdx.x * 32, p0 = blockIdx.y * 32;
    int tx = threadIdx.x, ty = threadIdx.y;   // (32, 8)
#pragma unroll
    for (int i = 0; i < 32; i += 8) {
        int p = p0 + ty + i, q = q0 + tx;
        if (p < P && q < Q) tile[ty + i][tx] = src[(size_t)p * Q + q];
    }
    __syncthreads();
#pragma unroll
    for (int i = 0; i < 32; i += 8) {
        int q = q0 + ty + i, p = p0 + tx;
        if (p < P && q < Q) dst[(size_t)q * P + p] = tile[tx][ty + i];
    }
}

// ======================= sine positional encoding ==========================
// pos[q][c]: c<128 -> y-features (v=row+1), c>=128 -> x-features (v=col+1)
// feature pair j: t = 10000^(2j/128); even->sin(v/t), odd->cos(v/t)
__global__ void pos_kernel(float* __restrict__ pos)
{
    int q = blockIdx.x;          // 0..HWn-1
    int c = threadIdx.x;         // 0..255
    int row = q / Wn, col = q % Wn;
    int cc = c;
    float v;
    if (cc < 128) { v = (float)(row + 1); }
    else          { v = (float)(col + 1); cc -= 128; }
    int j = cc >> 1;
    float t = powf(10000.f, (float)(2 * j) * (1.f / 128.f));
    float arg = v / t;
    pos[(size_t)q * Cn + c] = (cc & 1) ? cosf(arg) : sinf(arg);
}

// ======================= fp32 tiled GEMM ===================================
// C[M,N] = A[M,K] @ B[N,K]^T + bias[N]   (optional: A += pos[(m%posM),k], relu)
#define GBM 64
#define GBN 64
#define GBK 16

__global__ __launch_bounds__(256)
void gemm_kernel(const float* __restrict__ A, const float* __restrict__ B,
                 const float* __restrict__ bias, float* __restrict__ C,
                 int M, int N, int K,
                 const float* __restrict__ Apos, int posM, int relu)
{
    __shared__ float As[GBK][GBM + 4];
    __shared__ float Bs[GBK][GBN + 4];

    int tid = threadIdx.x;             // 256 threads
    int tx = tid & 15;                 // n-dir
    int ty = tid >> 4;                 // m-dir
    int m0 = blockIdx.y * GBM, n0 = blockIdx.x * GBN;

    int lm  = tid >> 2;                // 0..63 row within tile
    int lk4 = (tid & 3) << 2;          // 0,4,8,12

    float acc[4][4];
#pragma unroll
    for (int i = 0; i < 4; i++)
#pragma unroll
        for (int j = 0; j < 4; j++) acc[i][j] = 0.f;

    for (int k0 = 0; k0 < K; k0 += GBK) {
        // ---- load A tile (64 x 16), float4 per thread
        float4 av = make_float4(0.f, 0.f, 0.f, 0.f);
        int am = m0 + lm;
        if (am < M) {
            av = *(const float4*)(A + (size_t)am * K + k0 + lk4);
            if (Apos) {
                float4 pv = *(const float4*)(Apos + (size_t)(am % posM) * K + k0 + lk4);
                av.x += pv.x; av.y += pv.y; av.z += pv.z; av.w += pv.w;
            }
        }
        As[lk4 + 0][lm] = av.x; As[lk4 + 1][lm] = av.y;
        As[lk4 + 2][lm] = av.z; As[lk4 + 3][lm] = av.w;

        // ---- load B tile (64 x 16)
        float4 bv = make_float4(0.f, 0.f, 0.f, 0.f);
        int bn = n0 + lm;
        if (bn < N) bv = *(const float4*)(B + (size_t)bn * K + k0 + lk4);
        Bs[lk4 + 0][lm] = bv.x; Bs[lk4 + 1][lm] = bv.y;
        Bs[lk4 + 2][lm] = bv.z; Bs[lk4 + 3][lm] = bv.w;

        __syncthreads();

#pragma unroll
        for (int k = 0; k < GBK; k++) {
            float4 ra = *(const float4*)&As[k][ty * 4];
            float4 rb = *(const float4*)&Bs[k][tx * 4];
            float a[4] = {ra.x, ra.y, ra.z, ra.w};
            float b[4] = {rb.x, rb.y, rb.z, rb.w};
#pragma unroll
            for (int i = 0; i < 4; i++)
#pragma unroll
                for (int j = 0; j < 4; j++) acc[i][j] = fmaf(a[i], b[j], acc[i][j]);
        }
        __syncthreads();
    }

    // ---- epilogue
#pragma unroll
    for (int i = 0; i < 4; i++) {
        int m = m0 + ty * 4 + i;
        if (m >= M) continue;
#pragma unroll
        for (int j = 0; j < 4; j++) {
            int n = n0 + tx * 4 + j;
            if (n >= N) continue;
            float c = acc[i][j] + bias[n];
            if (relu) c = fmaxf(c, 0.f);
            C[(size_t)m * N + n] = c;
        }
    }
}

// ======================= deformable sampling ===============================
// one block per (q, b); 8 warps = 8 heads; lane = head-dim channel (32)
__global__ __launch_bounds__(256)
void sample_kernel(const float* __restrict__ value, const float* __restrict__ off,
                   const float* __restrict__ aw, float* __restrict__ attn)
{
    int q = blockIdx.x;
    int b = blockIdx.y;
    int h = threadIdx.x >> 5;
    int lane = threadIdx.x & 31;
    size_t base = (size_t)b * HWn + q;

    // softmax over 4 points
    const float* awp = aw + base * 32 + h * 4;
    float a0 = awp[0], a1 = awp[1], a2 = awp[2], a3 = awp[3];
    float mx = fmaxf(fmaxf(a0, a1), fmaxf(a2, a3));
    float e0 = expf(a0 - mx), e1 = expf(a1 - mx), e2 = expf(a2 - mx), e3 = expf(a3 - mx);
    float inv = 1.f / (e0 + e1 + e2 + e3);
    float wp[4] = {e0 * inv, e1 * inv, e2 * inv, e3 * inv};

    const float* offp = off + base * 64 + h * 8;
    int col = q % Wn, row = q / Wn;
    const float* vb = value + ((size_t)b * HWn) * Cn + h * HDn + lane;

    float acc = 0.f;
#pragma unroll
    for (int p = 0; p < 4; p++) {
        // x = col + off_x; y = row + off_y   (algebraic simplification of
        // (ref + off/norm)*size - 0.5 with ref at pixel centers)
        float x = (float)col + offp[p * 2 + 0];
        float y = (float)row + offp[p * 2 + 1];
        float xf = floorf(x), yf = floorf(y);
        int x0 = (int)xf, y0 = (int)yf;
        float wx = x - xf, wy = y - yf;
        float w00 = (1.f - wx) * (1.f - wy), w10 = wx * (1.f - wy);
        float w01 = (1.f - wx) * wy,         w11 = wx * wy;
        float s = 0.f;
        if ((unsigned)x0 < (unsigned)Wn && (unsigned)y0 < (unsigned)Hn)
            s += w00 * vb[(size_t)(y0 * Wn + x0) * Cn];
        if ((unsigned)(x0 + 1) < (unsigned)Wn && (unsigned)y0 < (unsigned)Hn)
            s += w10 * vb[(size_t)(y0 * Wn + x0 + 1) * Cn];
        if ((unsigned)x0 < (unsigned)Wn && (unsigned)(y0 + 1) < (unsigned)Hn)
            s += w01 * vb[(size_t)((y0 + 1) * Wn + x0) * Cn];
        if ((unsigned)(x0 + 1) < (unsigned)Wn && (unsigned)(y0 + 1) < (unsigned)Hn)
            s += w11 * vb[(size_t)((y0 + 1) * Wn + x0 + 1) * Cn];
        acc += wp[p] * s;
    }
    attn[base * Cn + h * HDn + lane] = acc;
}

// ======================= residual add + layernorm (in-place on x) =========
__global__ __launch_bounds__(256)
void add_ln_kernel(float* __restrict__ x, const float* __restrict__ r,
                   const float* __restrict__ g, const float* __restrict__ bta)
{
    size_t row = blockIdx.x;
    int c = threadIdx.x;
    float v = x[row * Cn + c] + r[row * Cn + c];

    __shared__ float sh[8], sh2[8];
    int w = c >> 5, lane = c & 31;

    float s = v;
#pragma unroll
    for (int o = 16; o > 0; o >>= 1) s += __shfl_xor_sync(0xffffffffu, s, o);
    if (lane == 0) sh[w] = s;
    __syncthreads();
    float tot = 0.f;
#pragma unroll
    for (int i = 0; i < 8; i++) tot += sh[i];
    float mean = tot * (1.f / 256.f);

    float d = v - mean;
    float s2 = d * d;
#pragma unroll
    for (int o = 16; o > 0; o >>= 1) s2 += __shfl_xor_sync(0xffffffffu, s2, o);
    if (lane == 0) sh2[w] = s2;
    __syncthreads();
    float var = 0.f;
#pragma unroll
    for (int i = 0; i < 8; i++) var += sh2[i];
    var *= (1.f / 256.f);

    x[row * Cn + c] = d * rsqrtf(var + 1e-5f) * g[c] + bta[c];
}

// ======================= launch ===========================================
extern "C" void kernel_launch(void* const* d_in, const int* in_sizes, int n_in,
                              void* d_out, int out_size)
{
    const float* bev      = (const float*)d_in[0];
    const float* proj_q_w = (const float*)d_in[1];
    const float* proj_q_b = (const float*)d_in[2];
    const float* off_w    = (const float*)d_in[3];
    const float* off_b    = (const float*)d_in[4];
    const float* aw_w     = (const float*)d_in[5];
    const float* aw_b     = (const float*)d_in[6];
    const float* vp_w     = (const float*)d_in[7];
    const float* vp_b     = (const float*)d_in[8];
    const float* op_w     = (const float*)d_in[9];
    const float* op_b     = (const float*)d_in[10];
    const float* ln1_g    = (const float*)d_in[11];
    const float* ln1_b    = (const float*)d_in[12];
    const float* l1_w     = (const float*)d_in[13];
    const float* l1_b     = (const float*)d_in[14];
    const float* l2_w     = (const float*)d_in[15];
    const float* l2_b     = (const float*)d_in[16];
    const float* ln2_g    = (const float*)d_in[17];
    const float* ln2_b    = (const float*)d_in[18];
    float* out_final      = (float*)d_out;

    float *out, *pos, *val, *attn, *offb, *awb;
    cudaGetSymbolAddress((void**)&out,  g_out);
    cudaGetSymbolAddress((void**)&pos,  g_pos);
    cudaGetSymbolAddress((void**)&val,  g_val);
    cudaGetSymbolAddress((void**)&attn, g_attn);
    cudaGetSymbolAddress((void**)&offb, g_off);
    cudaGetSymbolAddress((void**)&awb,  g_aw);

    dim3 tblk(32, 8);

    // 1. bev [b,C,HW] -> xbuf [b,HW,C]  (into attn scratch)
    {
        dim3 grid((HWn + 31) / 32, (Cn + 31) / 32, BSn);
        transpose_kernel<<<grid, tblk>>>(bev, attn, Cn, HWn);
    }
    // 2. positional encoding
    pos_kernel<<<HWn, 256>>>(pos);

    dim3 gemm_big((Cn + GBN - 1) / GBN, (Mn + GBM - 1) / GBM);   // (4,1250)
    dim3 gemm_off((64 + GBN - 1) / GBN, (Mn + GBM - 1) / GBM);   // (1,1250)
    dim3 gemm_aw ((32 + GBN - 1) / GBN, (Mn + GBM - 1) / GBM);   // (1,1250)

    // 3. out = x @ proj_q_w^T + b
    gemm_kernel<<<gemm_big, 256>>>(attn, proj_q_w, proj_q_b, out,
                                   Mn, Cn, Cn, nullptr, 0, 0);

    for (int i = 0; i < NLAYERS; i++) {
        const float* vpw = vp_w + (size_t)i * Cn * Cn;
        const float* vpb = vp_b + (size_t)i * Cn;
        const float* ofw = off_w + (size_t)i * 64 * Cn;
        const float* ofb = off_b + (size_t)i * 64;
        const float* aww = aw_w + (size_t)i * 32 * Cn;
        const float* awbb = aw_b + (size_t)i * 32;
        const float* opw = op_w + (size_t)i * Cn * Cn;
        const float* opb = op_b + (size_t)i * Cn;
        const float* l1w = l1_w + (size_t)i * Cn * Cn;
        const float* l1b = l1_b + (size_t)i * Cn;
        const float* l2w = l2_w + (size_t)i * Cn * Cn;
        const float* l2b = l2_b + (size_t)i * Cn;

        // value = out @ vp^T + b
        gemm_kernel<<<gemm_big, 256>>>(out, vpw, vpb, val,
                                       Mn, Cn, Cn, nullptr, 0, 0);
        // off = (out+pos) @ off^T + b ; aw_raw = (out+pos) @ aw^T + b
        gemm_kernel<<<gemm_off, 256>>>(out, ofw, ofb, offb,
                                       Mn, 64, Cn, pos, HWn, 0);
        gemm_kernel<<<gemm_aw, 256>>>(out, aww, awbb, awb,
                                      Mn, 32, Cn, pos, HWn, 0);
        // deformable sampling -> attn
        {
            dim3 sgrid(HWn, BSn);
            sample_kernel<<<sgrid, 256>>>(val, offb, awb, attn);
        }
        // attn2 = attn @ op^T + b  (into val)
        gemm_kernel<<<gemm_big, 256>>>(attn, opw, opb, val,
                                       Mn, Cn, Cn, nullptr, 0, 0);
        // out = LN(out + attn2)
        add_ln_kernel<<<Mn, 256>>>(out, val, ln1_g + (size_t)i * Cn, ln1_b + (size_t)i * Cn);
        // ffn1 = relu(out @ l1^T + b)  (into attn)
        gemm_kernel<<<gemm_big, 256>>>(out, l1w, l1b, attn,
                                       Mn, Cn, Cn, nullptr, 0, 1);
        // ffn2 = ffn1 @ l2^T + b  (into val)
        gemm_kernel<<<gemm_big, 256>>>(attn, l2w, l2b, val,
                                       Mn, Cn, Cn, nullptr, 0, 0);
        // out = LN(out + ffn2)
        add_ln_kernel<<<Mn, 256>>>(out, val, ln2_g + (size_t)i * Cn, ln2_b + (size_t)i * Cn);
    }

    // final: out [b,HW,C] -> d_out [b,C,HW]
    {
        dim3 grid((Cn + 31) / 32, (HWn + 31) / 32, BSn);
        transpose_kernel<<<grid, tblk>>>(out, out_final, HWn, Cn);
    }
}

// round 3
// speedup vs baseline: 1.6771x; 1.6771x over previous
#include <cuda_runtime.h>
#include <cuda_bf16.h>
#include <mma.h>
#include <cstdint>
#include <math.h>

using namespace nvcuda;

// Problem constants
#define BSn   2
#define Cn    256
#define Hn    200
#define Wn    200
#define HWn   (Hn * Wn)          // 40000
#define Mn    (BSn * HWn)        // 80000
#define NLAYERS 3
#define HDn   32

// -------- scratch (static device arrays; no allocation allowed) ----------
__device__ float g_out [ (size_t)Mn * Cn ];
__device__ float g_pos [ (size_t)HWn * Cn ];
__device__ float g_val [ (size_t)Mn * Cn ];
__device__ float g_attn[ (size_t)Mn * Cn ];
__device__ float g_off [ (size_t)Mn * 64 ];
__device__ float g_aw  [ (size_t)Mn * 32 ];

// ======================= bf16 hi/lo split helper ===========================
// packs 4 floats -> hi bf16x2 pair + lo (residual) bf16x2 pair
__device__ __forceinline__ void split4(float4 v, uint32_t& h01, uint32_t& h23,
                                       uint32_t& l01, uint32_t& l23)
{
    asm("cvt.rn.bf16x2.f32 %0, %1, %2;" : "=r"(h01) : "f"(v.y), "f"(v.x));
    asm("cvt.rn.bf16x2.f32 %0, %1, %2;" : "=r"(h23) : "f"(v.w), "f"(v.z));
    float r0 = v.x - __uint_as_float(h01 << 16);
    float r1 = v.y - __uint_as_float(h01 & 0xFFFF0000u);
    float r2 = v.z - __uint_as_float(h23 << 16);
    float r3 = v.w - __uint_as_float(h23 & 0xFFFF0000u);
    asm("cvt.rn.bf16x2.f32 %0, %1, %2;" : "=r"(l01) : "f"(r1), "f"(r0));
    asm("cvt.rn.bf16x2.f32 %0, %1, %2;" : "=r"(l23) : "f"(r3), "f"(r2));
}

__device__ __forceinline__ void sts_v2(uint32_t addr, uint32_t a, uint32_t b) {
    asm volatile("st.shared.v2.b32 [%0], {%1,%2};" :: "r"(addr), "r"(a), "r"(b) : "memory");
}

__device__ __forceinline__ uint32_t smem_u32(const void* p) {
    uint32_t a;
    asm("{ .reg .u64 t; cvta.to.shared.u64 t, %1; cvt.u32.u64 %0, t; }"
        : "=r"(a) : "l"(p));
    return a;
}

// ======================= WMMA bf16x3 GEMM ==================================
// C[M, N_OUT] = (A [+ pos]) @ B^T + bias ; A:[M,256] fp32, B:[N_OUT,256] fp32
// CTA tile: 128 x BN (BN = min(N_OUT,128)); K chunked by 64, single buffer.
// Three-term split: A_hi*B_hi + A_hi*B_lo + A_lo*B_hi (fp32 accumulate).
template<int N_OUT, bool ADD_POS, bool RELU>
__global__ __launch_bounds__(256)
void wgemm(const float* __restrict__ A, const float* __restrict__ B,
           const float* __restrict__ bias, float* __restrict__ C,
           const float* __restrict__ pos)
{
    constexpr int K = 256, KCH = 64, NCHUNK = K / KCH;
    constexpr int BN = (N_OUT >= 128) ? 128 : N_OUT;
    constexpr int WM = (BN == 128) ? 2 : (BN == 64 ? 4 : 8);
    constexpr int WN = 8 / WM;
    constexpr int MF = (128 / WM) / 16;     // m-frags per warp
    constexpr int NF = (BN / WN) / 16;      // n-frags per warp
    constexpr int STR = 72;                 // padded bf16 stride

    extern __shared__ char smem[];
    __nv_bfloat16* a_hi = (__nv_bfloat16*)smem;
    __nv_bfloat16* a_lo = a_hi + 128 * STR;
    __nv_bfloat16* b_hi = a_lo + 128 * STR;
    __nv_bfloat16* b_lo = b_hi + BN * STR;
    float* cs = (float*)smem;               // epilogue reuse

    uint32_t a_hi_u = smem_u32(a_hi), a_lo_u = smem_u32(a_lo);
    uint32_t b_hi_u = smem_u32(b_hi), b_lo_u = smem_u32(b_lo);

    int tid = threadIdx.x;
    int w = tid >> 5;
    int wm0 = (w / WN) * (128 / WM);
    int wn0 = (w % WN) * (BN / WN);
    int m0 = blockIdx.y * 128;
    int n0 = blockIdx.x * BN;

    wmma::fragment<wmma::accumulator, 16, 16, 16, float> acc[MF][NF];
#pragma unroll
    for (int i = 0; i < MF; i++)
#pragma unroll
        for (int j = 0; j < NF; j++) wmma::fill_fragment(acc[i][j], 0.f);

    for (int c = 0; c < NCHUNK; c++) {
        int k0 = c * KCH;
        if (c > 0) __syncthreads();   // previous compute done before overwrite

        // ---- A chunk: 128 x 64 fp32 -> bf16 hi/lo
#pragma unroll
        for (int it = 0; it < 8; it++) {
            int idx = tid + it * 256;
            int row = idx >> 4;
            int c4  = (idx & 15) << 2;
            float4 v = *(const float4*)(A + (size_t)(m0 + row) * K + k0 + c4);
            if (ADD_POS) {
                int m = m0 + row;
                int pm = m - (m >= HWn ? HWn : 0);
                float4 p = *(const float4*)(pos + (size_t)pm * K + k0 + c4);
                v.x += p.x; v.y += p.y; v.z += p.z; v.w += p.w;
            }
            uint32_t h01, h23, l01, l23;
            split4(v, h01, h23, l01, l23);
            uint32_t off = (uint32_t)(row * STR + c4) * 2;
            sts_v2(a_hi_u + off, h01, h23);
            sts_v2(a_lo_u + off, l01, l23);
        }
        // ---- B chunk: BN x 64
#pragma unroll
        for (int it = 0; it < BN / 16; it++) {
            int idx = tid + it * 256;
            int row = idx >> 4;
            int c4  = (idx & 15) << 2;
            float4 v = *(const float4*)(B + (size_t)(n0 + row) * K + k0 + c4);
            uint32_t h01, h23, l01, l23;
            split4(v, h01, h23, l01, l23);
            uint32_t off = (uint32_t)(row * STR + c4) * 2;
            sts_v2(b_hi_u + off, h01, h23);
            sts_v2(b_lo_u + off, l01, l23);
        }
        __syncthreads();

        // ---- compute 4 k-steps of 16
#pragma unroll
        for (int ks = 0; ks < 4; ks++) {
            wmma::fragment<wmma::matrix_a, 16, 16, 16, __nv_bfloat16, wmma::row_major> ah[MF], al[MF];
            wmma::fragment<wmma::matrix_b, 16, 16, 16, __nv_bfloat16, wmma::col_major> bh[NF], bl[NF];
#pragma unroll
            for (int i = 0; i < MF; i++) {
                const __nv_bfloat16* pa = a_hi + (wm0 + i * 16) * STR + ks * 16;
                wmma::load_matrix_sync(ah[i], pa, STR);
                wmma::load_matrix_sync(al[i], pa + 128 * STR, STR);
            }
#pragma unroll
            for (int j = 0; j < NF; j++) {
                const __nv_bfloat16* pb = b_hi + (wn0 + j * 16) * STR + ks * 16;
                wmma::load_matrix_sync(bh[j], pb, STR);
                wmma::load_matrix_sync(bl[j], pb + BN * STR, STR);
            }
#pragma unroll
            for (int i = 0; i < MF; i++)
#pragma unroll
                for (int j = 0; j < NF; j++) {
                    wmma::mma_sync(acc[i][j], ah[i], bh[j], acc[i][j]);
                    wmma::mma_sync(acc[i][j], ah[i], bl[j], acc[i][j]);
                    wmma::mma_sync(acc[i][j], al[i], bh[j], acc[i][j]);
                }
        }
    }

    // ---- epilogue via smem
    __syncthreads();
#pragma unroll
    for (int i = 0; i < MF; i++)
#pragma unroll
        for (int j = 0; j < NF; j++)
            wmma::store_matrix_sync(cs + (wm0 + i * 16) * (BN + 4) + wn0 + j * 16,
                                    acc[i][j], BN + 4, wmma::mem_row_major);
    __syncthreads();

    constexpr int ITERS = (128 * BN / 4) / 256;
#pragma unroll
    for (int it = 0; it < ITERS; it++) {
        int idx = tid + it * 256;
        int row = idx / (BN / 4);
        int c4  = (idx % (BN / 4)) * 4;
        float4 o = *(const float4*)(cs + row * (BN + 4) + c4);
        o.x += __ldg(bias + n0 + c4 + 0);
        o.y += __ldg(bias + n0 + c4 + 1);
        o.z += __ldg(bias + n0 + c4 + 2);
        o.w += __ldg(bias + n0 + c4 + 3);
        if (RELU) {
            o.x = fmaxf(o.x, 0.f); o.y = fmaxf(o.y, 0.f);
            o.z = fmaxf(o.z, 0.f); o.w = fmaxf(o.w, 0.f);
        }
        *(float4*)(C + (size_t)(m0 + row) * N_OUT + n0 + c4) = o;
    }
}

constexpr int wg_smem(int n_out) {
    int bn = (n_out >= 128) ? 128 : n_out;
    int ab = (2 * 128 + 2 * bn) * 72 * 2;
    int cb = 128 * (bn + 4) * 4;
    return ab > cb ? ab : cb;
}

// ======================= 32x32 tiled transpose =============================
__global__ void transpose_kernel(const float* __restrict__ src,
                                 float* __restrict__ dst, int P, int Q)
{
    __shared__ float tile[32][33];
    size_t zoff = (size_t)blockIdx.z * (size_t)P * (size_t)Q;
    src += zoff; dst += zoff;
    int q0 = blockIdx.x * 32, p0 = blockIdx.y * 32;
    int tx = threadIdx.x, ty = threadIdx.y;
#pragma unroll
    for (int i = 0; i < 32; i += 8) {
        int p = p0 + ty + i, q = q0 + tx;
        if (p < P && q < Q) tile[ty + i][tx] = src[(size_t)p * Q + q];
    }
    __syncthreads();
#pragma unroll
    for (int i = 0; i < 32; i += 8) {
        int q = q0 + ty + i, p = p0 + tx;
        if (p < P && q < Q) dst[(size_t)q * P + p] = tile[tx][ty + i];
    }
}

// ======================= sine positional encoding ==========================
__global__ void pos_kernel(float* __restrict__ pos)
{
    int q = blockIdx.x;
    int c = threadIdx.x;
    int row = q / Wn, col = q % Wn;
    int cc = c;
    float v;
    if (cc < 128) { v = (float)(row + 1); }
    else          { v = (float)(col + 1); cc -= 128; }
    int j = cc >> 1;
    float t = powf(10000.f, (float)(2 * j) * (1.f / 128.f));
    float arg = v / t;
    pos[(size_t)q * Cn + c] = (cc & 1) ? cosf(arg) : sinf(arg);
}

// ======================= deformable sampling ===============================
__global__ __launch_bounds__(256)
void sample_kernel(const float* __restrict__ value, const float* __restrict__ off,
                   const float* __restrict__ aw, float* __restrict__ attn)
{
    int q = blockIdx.x;
    int b = blockIdx.y;
    int h = threadIdx.x >> 5;
    int lane = threadIdx.x & 31;
    size_t base = (size_t)b * HWn + q;

    const float* awp = aw + base * 32 + h * 4;
    float a0 = awp[0], a1 = awp[1], a2 = awp[2], a3 = awp[3];
    float mx = fmaxf(fmaxf(a0, a1), fmaxf(a2, a3));
    float e0 = expf(a0 - mx), e1 = expf(a1 - mx), e2 = expf(a2 - mx), e3 = expf(a3 - mx);
    float inv = 1.f / (e0 + e1 + e2 + e3);
    float wp[4] = {e0 * inv, e1 * inv, e2 * inv, e3 * inv};

    const float* offp = off + base * 64 + h * 8;
    int col = q % Wn, row = q / Wn;
    const float* vb = value + ((size_t)b * HWn) * Cn + h * HDn + lane;

    float acc = 0.f;
#pragma unroll
    for (int p = 0; p < 4; p++) {
        float x = (float)col + offp[p * 2 + 0];
        float y = (float)row + offp[p * 2 + 1];
        float xf = floorf(x), yf = floorf(y);
        int x0 = (int)xf, y0 = (int)yf;
        float wx = x - xf, wy = y - yf;
        float w00 = (1.f - wx) * (1.f - wy), w10 = wx * (1.f - wy);
        float w01 = (1.f - wx) * wy,         w11 = wx * wy;
        float s = 0.f;
        if ((unsigned)x0 < (unsigned)Wn && (unsigned)y0 < (unsigned)Hn)
            s += w00 * vb[(size_t)(y0 * Wn + x0) * Cn];
        if ((unsigned)(x0 + 1) < (unsigned)Wn && (unsigned)y0 < (unsigned)Hn)
            s += w10 * vb[(size_t)(y0 * Wn + x0 + 1) * Cn];
        if ((unsigned)x0 < (unsigned)Wn && (unsigned)(y0 + 1) < (unsigned)Hn)
            s += w01 * vb[(size_t)((y0 + 1) * Wn + x0) * Cn];
        if ((unsigned)(x0 + 1) < (unsigned)Wn && (unsigned)(y0 + 1) < (unsigned)Hn)
            s += w11 * vb[(size_t)((y0 + 1) * Wn + x0 + 1) * Cn];
        acc += wp[p] * s;
    }
    attn[base * Cn + h * HDn + lane] = acc;
}

// ======================= residual add + layernorm ==========================
__global__ __launch_bounds__(256)
void add_ln_kernel(float* __restrict__ x, const float* __restrict__ r,
                   const float* __restrict__ g, const float* __restrict__ bta)
{
    size_t row = blockIdx.x;
    int c = threadIdx.x;
    float v = x[row * Cn + c] + r[row * Cn + c];

    __shared__ float sh[8], sh2[8];
    int w = c >> 5, lane = c & 31;

    float s = v;
#pragma unroll
    for (int o = 16; o > 0; o >>= 1) s += __shfl_xor_sync(0xffffffffu, s, o);
    if (lane == 0) sh[w] = s;
    __syncthreads();
    float tot = 0.f;
#pragma unroll
    for (int i = 0; i < 8; i++) tot += sh[i];
    float mean = tot * (1.f / 256.f);

    float d = v - mean;
    float s2 = d * d;
#pragma unroll
    for (int o = 16; o > 0; o >>= 1) s2 += __shfl_xor_sync(0xffffffffu, s2, o);
    if (lane == 0) sh2[w] = s2;
    __syncthreads();
    float var = 0.f;
#pragma unroll
    for (int i = 0; i < 8; i++) var += sh2[i];
    var *= (1.f / 256.f);

    x[row * Cn + c] = d * rsqrtf(var + 1e-5f) * g[c] + bta[c];
}

// ======================= launch ===========================================
extern "C" void kernel_launch(void* const* d_in, const int* in_sizes, int n_in,
                              void* d_out, int out_size)
{
    const float* bev      = (const float*)d_in[0];
    const float* proj_q_w = (const float*)d_in[1];
    const float* proj_q_b = (const float*)d_in[2];
    const float* off_w    = (const float*)d_in[3];
    const float* off_b    = (const float*)d_in[4];
    const float* aw_w     = (const float*)d_in[5];
    const float* aw_b     = (const float*)d_in[6];
    const float* vp_w     = (const float*)d_in[7];
    const float* vp_b     = (const float*)d_in[8];
    const float* op_w     = (const float*)d_in[9];
    const float* op_b     = (const float*)d_in[10];
    const float* ln1_g    = (const float*)d_in[11];
    const float* ln1_b    = (const float*)d_in[12];
    const float* l1_w     = (const float*)d_in[13];
    const float* l1_b     = (const float*)d_in[14];
    const float* l2_w     = (const float*)d_in[15];
    const float* l2_b     = (const float*)d_in[16];
    const float* ln2_g    = (const float*)d_in[17];
    const float* ln2_b    = (const float*)d_in[18];
    float* out_final      = (float*)d_out;

    float *out, *pos, *val, *attn, *offb, *awb;
    cudaGetSymbolAddress((void**)&out,  g_out);
    cudaGetSymbolAddress((void**)&pos,  g_pos);
    cudaGetSymbolAddress((void**)&val,  g_val);
    cudaGetSymbolAddress((void**)&attn, g_attn);
    cudaGetSymbolAddress((void**)&offb, g_off);
    cudaGetSymbolAddress((void**)&awb,  g_aw);

    cudaFuncSetAttribute(wgemm<256, false, false>,
                         cudaFuncAttributeMaxDynamicSharedMemorySize, wg_smem(256));
    cudaFuncSetAttribute(wgemm<256, false, true>,
                         cudaFuncAttributeMaxDynamicSharedMemorySize, wg_smem(256));
    cudaFuncSetAttribute(wgemm<64, true, false>,
                         cudaFuncAttributeMaxDynamicSharedMemorySize, wg_smem(64));
    cudaFuncSetAttribute(wgemm<32, true, false>,
                         cudaFuncAttributeMaxDynamicSharedMemorySize, wg_smem(32));

    dim3 tblk(32, 8);
    const int MB = Mn / 128;                 // 625
    dim3 g256(2, MB), g64(1, MB), g32(1, MB);

    // 1. bev [b,C,HW] -> xbuf [b,HW,C]
    {
        dim3 grid((HWn + 31) / 32, (Cn + 31) / 32, BSn);
        transpose_kernel<<<grid, tblk>>>(bev, attn, Cn, HWn);
    }
    // 2. positional encoding
    pos_kernel<<<HWn, 256>>>(pos);

    // 3. out = x @ proj_q_w^T + b
    wgemm<256, false, false><<<g256, 256, wg_smem(256)>>>(attn, proj_q_w, proj_q_b, out, nullptr);

    for (int i = 0; i < NLAYERS; i++) {
        const float* vpw = vp_w + (size_t)i * Cn * Cn;
        const float* vpb = vp_b + (size_t)i * Cn;
        const float* ofw = off_w + (size_t)i * 64 * Cn;
        const float* ofb = off_b + (size_t)i * 64;
        const float* aww = aw_w + (size_t)i * 32 * Cn;
        const float* awbb = aw_b + (size_t)i * 32;
        const float* opw = op_w + (size_t)i * Cn * Cn;
        const float* opb = op_b + (size_t)i * Cn;
        const float* l1w = l1_w + (size_t)i * Cn * Cn;
        const float* l1b = l1_b + (size_t)i * Cn;
        const float* l2w = l2_w + (size_t)i * Cn * Cn;
        const float* l2b = l2_b + (size_t)i * Cn;

        // value = out @ vp^T + b
        wgemm<256, false, false><<<g256, 256, wg_smem(256)>>>(out, vpw, vpb, val, nullptr);
        // off = (out+pos) @ off^T + b ; aw_raw = (out+pos) @ aw^T + b
        wgemm<64, true, false><<<g64, 256, wg_smem(64)>>>(out, ofw, ofb, offb, pos);
        wgemm<32, true, false><<<g32, 256, wg_smem(32)>>>(out, aww, awbb, awb, pos);
        // deformable sampling -> attn
        {
            dim3 sgrid(HWn, BSn);
            sample_kernel<<<sgrid, 256>>>(val, offb, awb, attn);
        }
        // attn2 = attn @ op^T + b
        wgemm<256, false, false><<<g256, 256, wg_smem(256)>>>(attn, opw, opb, val, nullptr);
        // out = LN(out + attn2)
        add_ln_kernel<<<Mn, 256>>>(out, val, ln1_g + (size_t)i * Cn, ln1_b + (size_t)i * Cn);
        // ffn1 = relu(out @ l1^T + b)
        wgemm<256, false, true><<<g256, 256, wg_smem(256)>>>(out, l1w, l1b, attn, nullptr);
        // ffn2 = ffn1 @ l2^T + b
        wgemm<256, false, false><<<g256, 256, wg_smem(256)>>>(attn, l2w, l2b, val, nullptr);
        // out = LN(out + ffn2)
        add_ln_kernel<<<Mn, 256>>>(out, val, ln2_g + (size_t)i * Cn, ln2_b + (size_t)i * Cn);
    }

    // final: out [b,HW,C] -> d_out [b,C,HW]
    {
        dim3 grid((Cn + 31) / 32, (HWn + 31) / 32, BSn);
        transpose_kernel<<<grid, tblk>>>(out, out_final, HWn, Cn);
    }
}

// round 4
// speedup vs baseline: 1.7659x; 1.0529x over previous
#include <cuda_runtime.h>
#include <cuda_bf16.h>
#include <mma.h>
#include <cstdint>
#include <math.h>

using namespace nvcuda;

// Problem constants
#define BSn   2
#define Cn    256
#define Hn    200
#define Wn    200
#define HWn   (Hn * Wn)          // 40000
#define Mn    (BSn * HWn)        // 80000
#define NLAYERS 3
#define HDn   32

// -------- scratch (static device arrays; no allocation allowed) ----------
__device__ float g_out [ (size_t)Mn * Cn ];
__device__ float g_pos [ (size_t)HWn * Cn ];
__device__ float g_val [ (size_t)Mn * Cn ];
__device__ float g_attn[ (size_t)Mn * Cn ];
__device__ float g_off [ (size_t)Mn * 64 ];
__device__ float g_aw  [ (size_t)Mn * 32 ];

// pre-split bf16 weights: [0]=proj, [1..3]=vp, [4..6]=op, [7..9]=l1, [10..12]=l2
__device__ __nv_bfloat16 g_wb_hi[13][65536];
__device__ __nv_bfloat16 g_wb_lo[13][65536];
// combined off(64)+aw(32) weights per layer: [3][96*256]
__device__ __nv_bfloat16 g_ow_hi[3][96 * 256];
__device__ __nv_bfloat16 g_ow_lo[3][96 * 256];
__device__ float g_obias[3][96];

// ======================= helpers ==========================================
__device__ __forceinline__ void split4(float4 v, uint32_t& h01, uint32_t& h23,
                                       uint32_t& l01, uint32_t& l23)
{
    asm("cvt.rn.bf16x2.f32 %0, %1, %2;" : "=r"(h01) : "f"(v.y), "f"(v.x));
    asm("cvt.rn.bf16x2.f32 %0, %1, %2;" : "=r"(h23) : "f"(v.w), "f"(v.z));
    float r0 = v.x - __uint_as_float(h01 << 16);
    float r1 = v.y - __uint_as_float(h01 & 0xFFFF0000u);
    float r2 = v.z - __uint_as_float(h23 << 16);
    float r3 = v.w - __uint_as_float(h23 & 0xFFFF0000u);
    asm("cvt.rn.bf16x2.f32 %0, %1, %2;" : "=r"(l01) : "f"(r1), "f"(r0));
    asm("cvt.rn.bf16x2.f32 %0, %1, %2;" : "=r"(l23) : "f"(r3), "f"(r2));
}

__device__ __forceinline__ void sts_v2(uint32_t addr, uint32_t a, uint32_t b) {
    asm volatile("st.shared.v2.b32 [%0], {%1,%2};" :: "r"(addr), "r"(a), "r"(b) : "memory");
}

__device__ __forceinline__ uint32_t smem_u32(const void* p) {
    uint32_t a;
    asm("{ .reg .u64 t; cvta.to.shared.u64 t, %1; cvt.u32.u64 %0, t; }"
        : "=r"(a) : "l"(p));
    return a;
}

__device__ __forceinline__ void cp_async16(uint32_t dst, const void* src) {
    asm volatile("cp.async.cg.shared.global [%0], [%1], 16;"
                 :: "r"(dst), "l"(src) : "memory");
}
__device__ __forceinline__ void cp_commit() {
    asm volatile("cp.async.commit_group;" ::: "memory");
}
__device__ __forceinline__ void cp_wait_all() {
    asm volatile("cp.async.wait_group 0;" ::: "memory");
}

// ======================= weight prep kernels ===============================
__global__ void conv_w_kernel(const float* __restrict__ src,
                              __nv_bfloat16* __restrict__ hi,
                              __nv_bfloat16* __restrict__ lo, int n)
{
    int i = (blockIdx.x * 256 + threadIdx.x) * 4;
    if (i >= n) return;
    float4 v = *(const float4*)(src + i);
    uint32_t h01, h23, l01, l23;
    split4(v, h01, h23, l01, l23);
    *(uint2*)((char*)hi + (size_t)i * 2) = make_uint2(h01, h23);
    *(uint2*)((char*)lo + (size_t)i * 2) = make_uint2(l01, l23);
}

__global__ void conv_ow_kernel(const float* __restrict__ off_w,
                               const float* __restrict__ aw_w)
{
    int idx = (blockIdx.x * 256 + threadIdx.x) * 4;   // over 3*96*256
    if (idx >= 3 * 96 * 256) return;
    int layer = idx / (96 * 256);
    int rem = idx - layer * 96 * 256;
    int r = rem >> 8, c = rem & 255;
    const float* src = (r < 64)
        ? off_w + ((size_t)layer * 64 + r) * 256 + c
        : aw_w + ((size_t)layer * 32 + (r - 64)) * 256 + c;
    float4 v = *(const float4*)src;
    uint32_t h01, h23, l01, l23;
    split4(v, h01, h23, l01, l23);
    *(uint2*)((char*)&g_ow_hi[layer][rem] ) = make_uint2(h01, h23);
    *(uint2*)((char*)&g_ow_lo[layer][rem] ) = make_uint2(l01, l23);
}

__global__ void conv_obias_kernel(const float* __restrict__ off_b,
                                  const float* __restrict__ aw_b)
{
    int idx = threadIdx.x;                 // 288 threads = 3*96
    if (idx >= 3 * 96) return;
    int layer = idx / 96, r = idx % 96;
    g_obias[layer][r] = (r < 64) ? off_b[layer * 64 + r] : aw_b[layer * 32 + (r - 64)];
}

// ======================= pipelined WMMA bf16x3 GEMM ========================
// C[M, BN*grid.x] = (A [+pos]) @ B^T + bias ; A fp32 [M,256], B pre-split bf16.
// CTA tile 128 x BN. K chunks of 64, double-buffered, cp.async for B.
template<int BN, int N_OUT, bool ADD_POS, bool RELU, bool SPLIT>
__global__ __launch_bounds__(256)
void wgemm(const float* __restrict__ A,
           const __nv_bfloat16* __restrict__ Bh,
           const __nv_bfloat16* __restrict__ Bl,
           const float* __restrict__ bias, float* __restrict__ C,
           float* __restrict__ C2, const float* __restrict__ pos)
{
    constexpr int K = 256, KCH = 64, NCHUNK = K / KCH;
    constexpr int WM = (BN == 128) ? 2 : 4;
    constexpr int WN = 8 / WM;
    constexpr int MF = (128 / WM) / 16;
    constexpr int NF = (BN / WN) / 16;
    constexpr int STR = 72;                              // bf16 padded stride
    constexpr int ABYTES = 128 * STR * 2;                // one A split buffer
    constexpr int BBYTES = BN * STR * 2;
    constexpr int STAGE = 2 * ABYTES + 2 * BBYTES;

    extern __shared__ char smem[];
    uint32_t sbase = smem_u32(smem);
    float* cs = (float*)smem;

    int tid = threadIdx.x;
    int w = tid >> 5;
    int wm0 = (w / WN) * (128 / WM);
    int wn0 = (w % WN) * (BN / WN);
    int m0 = blockIdx.y * 128;
    int n0 = blockIdx.x * BN;

    wmma::fragment<wmma::accumulator, 16, 16, 16, float> acc[MF][NF];
#pragma unroll
    for (int i = 0; i < MF; i++)
#pragma unroll
        for (int j = 0; j < NF; j++) wmma::fill_fragment(acc[i][j], 0.f);

    // per-thread A chunk registers (128x64 fp32 across 256 threads)
    float4 areg[8];
    const int arow = tid >> 4;             // 0..15 (x8 iters -> 128 rows)
    const int ac4  = (tid & 15) << 2;

    auto load_A = [&](int c) {
        int k0 = c * KCH;
#pragma unroll
        for (int it = 0; it < 8; it++) {
            int row = arow + it * 16;
            int m = m0 + row;
            float4 v = *(const float4*)(A + (size_t)m * K + k0 + ac4);
            if (ADD_POS) {
                int pm = m - (m >= HWn ? HWn : 0);
                float4 p = *(const float4*)(pos + (size_t)pm * K + k0 + ac4);
                v.x += p.x; v.y += p.y; v.z += p.z; v.w += p.w;
            }
            areg[it] = v;
        }
    };
    auto sts_A = [&](int c) {
        uint32_t a_hi = sbase + (c & 1) * STAGE;
        uint32_t a_lo = a_hi + ABYTES;
#pragma unroll
        for (int it = 0; it < 8; it++) {
            int row = arow + it * 16;
            uint32_t h01, h23, l01, l23;
            split4(areg[it], h01, h23, l01, l23);
            uint32_t off = (uint32_t)(row * STR + ac4) * 2;
            sts_v2(a_hi + off, h01, h23);
            sts_v2(a_lo + off, l01, l23);
        }
    };
    auto cp_B = [&](int c) {
        int k0 = c * KCH;
        uint32_t b_hi = sbase + (c & 1) * STAGE + 2 * ABYTES;
#pragma unroll
        for (int it = 0; it < BN / 16; it++) {
            int idx = tid + it * 256;
            int half = idx / (BN * 8);
            int rem = idx - half * BN * 8;
            int r = rem >> 3, ch = rem & 7;
            const __nv_bfloat16* src =
                (half ? Bl : Bh) + (size_t)(n0 + r) * K + k0 + ch * 8;
            uint32_t dst = b_hi + half * BBYTES + (uint32_t)(r * STR + ch * 8) * 2;
            cp_async16(dst, src);
        }
        cp_commit();
    };

    // prologue
    load_A(0);
    sts_A(0);
    cp_B(0);

    for (int c = 0; c < NCHUNK; c++) {
        cp_wait_all();
        __syncthreads();
        if (c + 1 < NCHUNK) { cp_B(c + 1); load_A(c + 1); }

        const __nv_bfloat16* a_hi =
            (const __nv_bfloat16*)(smem + (c & 1) * STAGE);
        const __nv_bfloat16* b_hi =
            (const __nv_bfloat16*)(smem + (c & 1) * STAGE + 2 * ABYTES);
#pragma unroll
        for (int ks = 0; ks < 4; ks++) {
            wmma::fragment<wmma::matrix_a, 16, 16, 16, __nv_bfloat16, wmma::row_major> ah[MF], al[MF];
            wmma::fragment<wmma::matrix_b, 16, 16, 16, __nv_bfloat16, wmma::col_major> bh[NF], bl[NF];
#pragma unroll
            for (int i = 0; i < MF; i++) {
                const __nv_bfloat16* pa = a_hi + (wm0 + i * 16) * STR + ks * 16;
                wmma::load_matrix_sync(ah[i], pa, STR);
                wmma::load_matrix_sync(al[i], pa + 128 * STR, STR);
            }
#pragma unroll
            for (int j = 0; j < NF; j++) {
                const __nv_bfloat16* pb = b_hi + (wn0 + j * 16) * STR + ks * 16;
                wmma::load_matrix_sync(bh[j], pb, STR);
                wmma::load_matrix_sync(bl[j], pb + BN * STR, STR);
            }
#pragma unroll
            for (int i = 0; i < MF; i++)
#pragma unroll
                for (int j = 0; j < NF; j++) {
                    wmma::mma_sync(acc[i][j], ah[i], bh[j], acc[i][j]);
                    wmma::mma_sync(acc[i][j], ah[i], bl[j], acc[i][j]);
                    wmma::mma_sync(acc[i][j], al[i], bh[j], acc[i][j]);
                }
        }
        if (c + 1 < NCHUNK) sts_A(c + 1);
    }

    // ---- epilogue via smem (reuse stage buffers)
    __syncthreads();
#pragma unroll
    for (int i = 0; i < MF; i++)
#pragma unroll
        for (int j = 0; j < NF; j++)
            wmma::store_matrix_sync(cs + (wm0 + i * 16) * (BN + 4) + wn0 + j * 16,
                                    acc[i][j], BN + 4, wmma::mem_row_major);
    __syncthreads();

    constexpr int ITERS = BN / 8;
#pragma unroll
    for (int it = 0; it < ITERS; it++) {
        int idx = tid + it * 256;
        int row = idx / (BN / 4);
        int c4  = (idx % (BN / 4)) * 4;
        float4 o = *(const float4*)(cs + row * (BN + 4) + c4);
        o.x += __ldg(bias + n0 + c4 + 0);
        o.y += __ldg(bias + n0 + c4 + 1);
        o.z += __ldg(bias + n0 + c4 + 2);
        o.w += __ldg(bias + n0 + c4 + 3);
        if (RELU) {
            o.x = fmaxf(o.x, 0.f); o.y = fmaxf(o.y, 0.f);
            o.z = fmaxf(o.z, 0.f); o.w = fmaxf(o.w, 0.f);
        }
        if (SPLIT) {
            int m = m0 + row;
            if (c4 < 64) *(float4*)(C  + (size_t)m * 64 + c4)        = o;
            else         *(float4*)(C2 + (size_t)m * 32 + (c4 - 64)) = o;
        } else {
            *(float4*)(C + (size_t)(m0 + row) * N_OUT + n0 + c4) = o;
        }
    }
}

constexpr int wg_smem(int bn) {
    int stage = (2 * 128 + 2 * bn) * 72 * 2;
    int ab = 2 * stage;
    int cb = 128 * (bn + 4) * 4;
    return ab > cb ? ab : cb;
}

// ======================= 32x32 tiled transpose =============================
__global__ void transpose_kernel(const float* __restrict__ src,
                                 float* __restrict__ dst, int P, int Q)
{
    __shared__ float tile[32][33];
    size_t zoff = (size_t)blockIdx.z * (size_t)P * (size_t)Q;
    src += zoff; dst += zoff;
    int q0 = blockIdx.x * 32, p0 = blockIdx.y * 32;
    int tx = threadIdx.x, ty = threadIdx.y;
#pragma unroll
    for (int i = 0; i < 32; i += 8) {
        int p = p0 + ty + i, q = q0 + tx;
        if (p < P && q < Q) tile[ty + i][tx] = src[(size_t)p * Q + q];
    }
    __syncthreads();
#pragma unroll
    for (int i = 0; i < 32; i += 8) {
        int q = q0 + ty + i, p = p0 + tx;
        if (p < P && q < Q) dst[(size_t)q * P + p] = tile[tx][ty + i];
    }
}

// ======================= sine positional encoding ==========================
__global__ void pos_kernel(float* __restrict__ pos)
{
    int q = blockIdx.x;
    int c = threadIdx.x;
    int row = q / Wn, col = q % Wn;
    int cc = c;
    float v;
    if (cc < 128) { v = (float)(row + 1); }
    else          { v = (float)(col + 1); cc -= 128; }
    int j = cc >> 1;
    float t = powf(10000.f, (float)(2 * j) * (1.f / 128.f));
    float arg = v / t;
    pos[(size_t)q * Cn + c] = (cc & 1) ? cosf(arg) : sinf(arg);
}

// ======================= deformable sampling ===============================
__global__ __launch_bounds__(256)
void sample_kernel(const float* __restrict__ value, const float* __restrict__ off,
                   const float* __restrict__ aw, float* __restrict__ attn)
{
    int q = blockIdx.x;
    int b = blockIdx.y;
    int h = threadIdx.x >> 5;
    int lane = threadIdx.x & 31;
    size_t base = (size_t)b * HWn + q;

    const float* awp = aw + base * 32 + h * 4;
    float a0 = awp[0], a1 = awp[1], a2 = awp[2], a3 = awp[3];
    float mx = fmaxf(fmaxf(a0, a1), fmaxf(a2, a3));
    float e0 = expf(a0 - mx), e1 = expf(a1 - mx), e2 = expf(a2 - mx), e3 = expf(a3 - mx);
    float inv = 1.f / (e0 + e1 + e2 + e3);
    float wp[4] = {e0 * inv, e1 * inv, e2 * inv, e3 * inv};

    const float* offp = off + base * 64 + h * 8;
    int col = q % Wn, row = q / Wn;
    const float* vb = value + ((size_t)b * HWn) * Cn + h * HDn + lane;

    float acc = 0.f;
#pragma unroll
    for (int p = 0; p < 4; p++) {
        float x = (float)col + offp[p * 2 + 0];
        float y = (float)row + offp[p * 2 + 1];
        float xf = floorf(x), yf = floorf(y);
        int x0 = (int)xf, y0 = (int)yf;
        float wx = x - xf, wy = y - yf;
        float w00 = (1.f - wx) * (1.f - wy), w10 = wx * (1.f - wy);
        float w01 = (1.f - wx) * wy,         w11 = wx * wy;
        float s = 0.f;
        if ((unsigned)x0 < (unsigned)Wn && (unsigned)y0 < (unsigned)Hn)
            s += w00 * vb[(size_t)(y0 * Wn + x0) * Cn];
        if ((unsigned)(x0 + 1) < (unsigned)Wn && (unsigned)y0 < (unsigned)Hn)
            s += w10 * vb[(size_t)(y0 * Wn + x0 + 1) * Cn];
        if ((unsigned)x0 < (unsigned)Wn && (unsigned)(y0 + 1) < (unsigned)Hn)
            s += w01 * vb[(size_t)((y0 + 1) * Wn + x0) * Cn];
        if ((unsigned)(x0 + 1) < (unsigned)Wn && (unsigned)(y0 + 1) < (unsigned)Hn)
            s += w11 * vb[(size_t)((y0 + 1) * Wn + x0 + 1) * Cn];
        acc += wp[p] * s;
    }
    attn[base * Cn + h * HDn + lane] = acc;
}

// ======================= residual add + layernorm ==========================
__global__ __launch_bounds__(256)
void add_ln_kernel(float* __restrict__ x, const float* __restrict__ r,
                   const float* __restrict__ g, const float* __restrict__ bta)
{
    size_t row = blockIdx.x;
    int c = threadIdx.x;
    float v = x[row * Cn + c] + r[row * Cn + c];

    __shared__ float sh[8], sh2[8];
    int w = c >> 5, lane = c & 31;

    float s = v;
#pragma unroll
    for (int o = 16; o > 0; o >>= 1) s += __shfl_xor_sync(0xffffffffu, s, o);
    if (lane == 0) sh[w] = s;
    __syncthreads();
    float tot = 0.f;
#pragma unroll
    for (int i = 0; i < 8; i++) tot += sh[i];
    float mean = tot * (1.f / 256.f);

    float d = v - mean;
    float s2 = d * d;
#pragma unroll
    for (int o = 16; o > 0; o >>= 1) s2 += __shfl_xor_sync(0xffffffffu, s2, o);
    if (lane == 0) sh2[w] = s2;
    __syncthreads();
    float var = 0.f;
#pragma unroll
    for (int i = 0; i < 8; i++) var += sh2[i];
    var *= (1.f / 256.f);

    x[row * Cn + c] = d * rsqrtf(var + 1e-5f) * g[c] + bta[c];
}

// ======================= launch ===========================================
extern "C" void kernel_launch(void* const* d_in, const int* in_sizes, int n_in,
                              void* d_out, int out_size)
{
    const float* bev      = (const float*)d_in[0];
    const float* proj_q_w = (const float*)d_in[1];
    const float* proj_q_b = (const float*)d_in[2];
    const float* off_w    = (const float*)d_in[3];
    const float* off_b    = (const float*)d_in[4];
    const float* aw_w     = (const float*)d_in[5];
    const float* aw_b     = (const float*)d_in[6];
    const float* vp_w     = (const float*)d_in[7];
    const float* vp_b     = (const float*)d_in[8];
    const float* op_w     = (const float*)d_in[9];
    const float* op_b     = (const float*)d_in[10];
    const float* ln1_g    = (const float*)d_in[11];
    const float* ln1_b    = (const float*)d_in[12];
    const float* l1_w     = (const float*)d_in[13];
    const float* l1_b     = (const float*)d_in[14];
    const float* l2_w     = (const float*)d_in[15];
    const float* l2_b     = (const float*)d_in[16];
    const float* ln2_g    = (const float*)d_in[17];
    const float* ln2_b    = (const float*)d_in[18];
    float* out_final      = (float*)d_out;

    float *out, *pos, *val, *attn, *offb, *awb;
    cudaGetSymbolAddress((void**)&out,  g_out);
    cudaGetSymbolAddress((void**)&pos,  g_pos);
    cudaGetSymbolAddress((void**)&val,  g_val);
    cudaGetSymbolAddress((void**)&attn, g_attn);
    cudaGetSymbolAddress((void**)&offb, g_off);
    cudaGetSymbolAddress((void**)&awb,  g_aw);

    __nv_bfloat16 *wbh, *wbl, *owh, *owl;
    float* obias;
    cudaGetSymbolAddress((void**)&wbh, g_wb_hi);
    cudaGetSymbolAddress((void**)&wbl, g_wb_lo);
    cudaGetSymbolAddress((void**)&owh, g_ow_hi);
    cudaGetSymbolAddress((void**)&owl, g_ow_lo);
    cudaGetSymbolAddress((void**)&obias, g_obias);

    cudaFuncSetAttribute((const void*)wgemm<128, 256, false, false, false>,
                         cudaFuncAttributeMaxDynamicSharedMemorySize, wg_smem(128));
    cudaFuncSetAttribute((const void*)wgemm<128, 256, false, true, false>,
                         cudaFuncAttributeMaxDynamicSharedMemorySize, wg_smem(128));
    cudaFuncSetAttribute((const void*)wgemm<96, 96, true, false, true>,
                         cudaFuncAttributeMaxDynamicSharedMemorySize, wg_smem(96));

    // ---- weight prep
    conv_w_kernel<<<64, 256>>>(proj_q_w, wbh + 0 * 65536, wbl + 0 * 65536, 65536);
    conv_w_kernel<<<192, 256>>>(vp_w, wbh + 1 * 65536, wbl + 1 * 65536, 3 * 65536);
    conv_w_kernel<<<192, 256>>>(op_w, wbh + 4 * 65536, wbl + 4 * 65536, 3 * 65536);
    conv_w_kernel<<<192, 256>>>(l1_w, wbh + 7 * 65536, wbl + 7 * 65536, 3 * 65536);
    conv_w_kernel<<<192, 256>>>(l2_w, wbh + 10 * 65536, wbl + 10 * 65536, 3 * 65536);
    conv_ow_kernel<<<72, 256>>>(off_w, aw_w);
    conv_obias_kernel<<<1, 288>>>(off_b, aw_b);

    dim3 tblk(32, 8);
    const int MB = Mn / 128;               // 625
    dim3 g256(2, MB), g96(1, MB);

    // 1. bev [b,C,HW] -> xbuf [b,HW,C]
    {
        dim3 grid((HWn + 31) / 32, (Cn + 31) / 32, BSn);
        transpose_kernel<<<grid, tblk>>>(bev, attn, Cn, HWn);
    }
    // 2. positional encoding
    pos_kernel<<<HWn, 256>>>(pos);

    // 3. out = x @ proj_q_w^T + b
    wgemm<128, 256, false, false, false><<<g256, 256, wg_smem(128)>>>(
        attn, wbh + 0 * 65536, wbl + 0 * 65536, proj_q_b, out, nullptr, nullptr);

    for (int i = 0; i < NLAYERS; i++) {
        const float* vpb = vp_b + (size_t)i * Cn;
        const float* opb = op_b + (size_t)i * Cn;
        const float* l1b = l1_b + (size_t)i * Cn;
        const float* l2b = l2_b + (size_t)i * Cn;

        // value = out @ vp^T + b
        wgemm<128, 256, false, false, false><<<g256, 256, wg_smem(128)>>>(
            out, wbh + (size_t)(1 + i) * 65536, wbl + (size_t)(1 + i) * 65536,
            vpb, val, nullptr, nullptr);
        // fused: off | aw = (out+pos) @ [off_w;aw_w]^T + [off_b;aw_b]
        wgemm<96, 96, true, false, true><<<g96, 256, wg_smem(96)>>>(
            out, owh + (size_t)i * 96 * 256, owl + (size_t)i * 96 * 256,
            obias + (size_t)i * 96, offb, awb, pos);
        // deformable sampling -> attn
        {
            dim3 sgrid(HWn, BSn);
            sample_kernel<<<sgrid, 256>>>(val, offb, awb, attn);
        }
        // attn2 = attn @ op^T + b
        wgemm<128, 256, false, false, false><<<g256, 256, wg_smem(128)>>>(
            attn, wbh + (size_t)(4 + i) * 65536, wbl + (size_t)(4 + i) * 65536,
            opb, val, nullptr, nullptr);
        // out = LN(out + attn2)
        add_ln_kernel<<<Mn, 256>>>(out, val, ln1_g + (size_t)i * Cn, ln1_b + (size_t)i * Cn);
        // ffn1 = relu(out @ l1^T + b)
        wgemm<128, 256, false, true, false><<<g256, 256, wg_smem(128)>>>(
            out, wbh + (size_t)(7 + i) * 65536, wbl + (size_t)(7 + i) * 65536,
            l1b, attn, nullptr, nullptr);
        // ffn2 = ffn1 @ l2^T + b
        wgemm<128, 256, false, false, false><<<g256, 256, wg_smem(128)>>>(
            attn, wbh + (size_t)(10 + i) * 65536, wbl + (size_t)(10 + i) * 65536,
            l2b, val, nullptr, nullptr);
        // out = LN(out + ffn2)
        add_ln_kernel<<<Mn, 256>>>(out, val, ln2_g + (size_t)i * Cn, ln2_b + (size_t)i * Cn);
    }

    // final: out [b,HW,C] -> d_out [b,C,HW]
    {
        dim3 grid((Cn + 31) / 32, (HWn + 31) / 32, BSn);
        transpose_kernel<<<grid, tblk>>>(out, out_final, HWn, Cn);
    }
}